// round 5
// baseline (speedup 1.0000x reference)
#include <cuda_runtime.h>

#define Tv 512
#define ROWW 60   // floats per smem row: 56 data + 4 pad (240B, 16B-aligned)

typedef unsigned long long u64;

__device__ __forceinline__ u64 PK(float a, float b) {
    u64 r; asm("mov.b64 %0,{%1,%2};" : "=l"(r) : "r"(__float_as_uint(a)), "r"(__float_as_uint(b))); return r;
}
__device__ __forceinline__ void UPK(u64 v, float& a, float& b) {
    unsigned x, y; asm("mov.b64 {%0,%1},%2;" : "=r"(x), "=r"(y) : "l"(v));
    a = __uint_as_float(x); b = __uint_as_float(y);
}
__device__ __forceinline__ u64 FMA2(u64 a, u64 b, u64 c) {
    u64 d; asm("fma.rn.f32x2 %0,%1,%2,%3;" : "=l"(d) : "l"(a), "l"(b), "l"(c)); return d;
}
__device__ __forceinline__ u64 MUL2(u64 a, u64 b) {
    u64 d; asm("mul.rn.f32x2 %0,%1,%2;" : "=l"(d) : "l"(a), "l"(b)); return d;
}
__device__ __forceinline__ void cpa16(float* dst, const void* src) {
    unsigned d = (unsigned)__cvta_generic_to_shared(dst);
    asm volatile("cp.async.cg.shared.global [%0], [%1], 16;" :: "r"(d), "l"(src));
}
#define CP_COMMIT() asm volatile("cp.async.commit_group;")
#define CP_WAIT2()  asm volatile("cp.async.wait_group 2;")

__global__ void __launch_bounds__(96, 1)
crf_fwd_kernel(const float* __restrict__ em,
               const int* __restrict__ labels,
               const int* __restrict__ mask,
               const float* __restrict__ startT,
               const float* __restrict__ endT,
               const float* __restrict__ trans,
               float* __restrict__ out)
{
    __shared__ float sm[2][3][32 * ROWW];
    __shared__ float sTrans[49];

    const int tid  = threadIdx.x;
    const int wid  = tid >> 5;
    const int lane = tid & 31;

    for (int i = tid; i < 49; i += 96) sTrans[i] = trans[i];
    __syncthreads();

    // ================= numerator warp =================
    if (wid == 2) {
        float acc = 0.0f;
#pragma unroll 1
        for (int s = 0; s < 2; s++) {
            const int bb = blockIdx.x * 64 + s * 32 + lane;
            const float* e = em + (size_t)bb * (Tv * 7);
            const int4* lp = (const int4*)(labels + (size_t)bb * Tv);
            const int4* mp = (const int4*)(mask + (size_t)bb * Tv);

            int4 l4 = __ldg(lp), m4 = __ldg(mp);
            int L0 = l4.x < 0 ? 0 : l4.x;
            float num = __ldg(startT + L0) + __ldg(e + L0);
            int prev = L0;

            // steps 1..3 of the first group
            {
                int Lc;
                Lc = l4.y < 0 ? 0 : l4.y;
                { float v = sTrans[prev*7+Lc] + __ldg(e + 7 + Lc);  num += m4.y ? v : 0.f; prev = m4.y ? Lc : prev; }
                Lc = l4.z < 0 ? 0 : l4.z;
                { float v = sTrans[prev*7+Lc] + __ldg(e + 14 + Lc); num += m4.z ? v : 0.f; prev = m4.z ? Lc : prev; }
                Lc = l4.w < 0 ? 0 : l4.w;
                { float v = sTrans[prev*7+Lc] + __ldg(e + 21 + Lc); num += m4.w ? v : 0.f; prev = m4.w ? Lc : prev; }
            }
            int4 lN = __ldg(lp + 1), mN = __ldg(mp + 1);
#pragma unroll 1
            for (int g = 1; g < 128; g++) {
                int4 lc = lN, mc = mN;
                if (g + 1 < 128) { lN = __ldg(lp + g + 1); mN = __ldg(mp + g + 1); }
                const float* eg = e + g * 28;
                int Lc;
                Lc = lc.x < 0 ? 0 : lc.x;
                { float v = sTrans[prev*7+Lc] + __ldg(eg + Lc);      num += mc.x ? v : 0.f; prev = mc.x ? Lc : prev; }
                Lc = lc.y < 0 ? 0 : lc.y;
                { float v = sTrans[prev*7+Lc] + __ldg(eg + 7 + Lc);  num += mc.y ? v : 0.f; prev = mc.y ? Lc : prev; }
                Lc = lc.z < 0 ? 0 : lc.z;
                { float v = sTrans[prev*7+Lc] + __ldg(eg + 14 + Lc); num += mc.z ? v : 0.f; prev = mc.z ? Lc : prev; }
                Lc = lc.w < 0 ? 0 : lc.w;
                { float v = sTrans[prev*7+Lc] + __ldg(eg + 21 + Lc); num += mc.w ? v : 0.f; prev = mc.w ? Lc : prev; }
            }
            num += __ldg(endT + prev);
            acc += num;
        }
#pragma unroll
        for (int off = 16; off > 0; off >>= 1)
            acc += __shfl_xor_sync(0xFFFFFFFFu, acc, off);
        if (lane == 0) atomicAdd(out, -acc);
        return;
    }

    // ================= forward warps (wid 0,1) =================
    const float* ebw = em + (size_t)(blockIdx.x * 64 + wid * 32) * (Tv * 7);
    const int b = blockIdx.x * 64 + tid;
    const int4* mb4 = (const int4*)(mask + (size_t)b * Tv);

    // exp(transitions): packed pairs cols 0-5, scalar col 6
    u64 EP[7][3]; float E6[7];
#pragma unroll
    for (int i = 0; i < 7; i++) {
        float e0 = __expf(__ldg(&trans[i*7+0])), e1 = __expf(__ldg(&trans[i*7+1]));
        float e2 = __expf(__ldg(&trans[i*7+2])), e3 = __expf(__ldg(&trans[i*7+3]));
        float e4 = __expf(__ldg(&trans[i*7+4])), e5 = __expf(__ldg(&trans[i*7+5]));
        EP[i][0] = PK(e0,e1); EP[i][1] = PK(e2,e3); EP[i][2] = PK(e4,e5);
        E6[i] = __expf(__ldg(&trans[i*7+6]));
    }

#define STAGE(MM) do { \
    float* _base = &sm[wid][(MM) % 3][0]; \
    const float* _g = ebw + (MM) * 56; \
    _Pragma("unroll") \
    for (int i = 0; i < 14; i++) { \
        int idx = i * 32 + lane; \
        int r = (idx * 4682) >> 16;     /* exact /14 for idx<448 */ \
        int c = idx - r * 14; \
        cpa16(_base + r * ROWW + c * 4, _g + (size_t)r * (Tv*7) + c * 4); \
    } \
    CP_COMMIT(); } while (0)

    u64 p01, p23, p45; float p6;
    int xsum = 0;

    const float* myrow0 = &sm[wid][0][lane * ROWW];
    const float* myrow1 = &sm[wid][1][lane * ROWW];
    const float* myrow2 = &sm[wid][2][lane * ROWW];

    // one recursion step; ep -> 7 raw emissions in smem
    auto STEP = [&](const float* ep, int M) {
        float x0=__expf(ep[0]), x1=__expf(ep[1]), x2=__expf(ep[2]), x3=__expf(ep[3]);
        float x4=__expf(ep[4]), x5=__expf(ep[5]), x6=__expf(ep[6]);
        float a0,a1,a2,a3,a4,a5;
        UPK(p01,a0,a1); UPK(p23,a2,a3); UPK(p45,a4,a5);
        u64 bb, q01, q23, q45; float q6;
        bb = PK(a0,a0);
        q01 = MUL2(bb,EP[0][0]); q23 = MUL2(bb,EP[0][1]); q45 = MUL2(bb,EP[0][2]);
        q6 = a0 * E6[0];
        bb = PK(a1,a1);
        q01 = FMA2(bb,EP[1][0],q01); q23 = FMA2(bb,EP[1][1],q23); q45 = FMA2(bb,EP[1][2],q45);
        q6 = fmaf(a1,E6[1],q6);
        bb = PK(a2,a2);
        q01 = FMA2(bb,EP[2][0],q01); q23 = FMA2(bb,EP[2][1],q23); q45 = FMA2(bb,EP[2][2],q45);
        q6 = fmaf(a2,E6[2],q6);
        bb = PK(a3,a3);
        q01 = FMA2(bb,EP[3][0],q01); q23 = FMA2(bb,EP[3][1],q23); q45 = FMA2(bb,EP[3][2],q45);
        q6 = fmaf(a3,E6[3],q6);
        bb = PK(a4,a4);
        q01 = FMA2(bb,EP[4][0],q01); q23 = FMA2(bb,EP[4][1],q23); q45 = FMA2(bb,EP[4][2],q45);
        q6 = fmaf(a4,E6[4],q6);
        bb = PK(a5,a5);
        q01 = FMA2(bb,EP[5][0],q01); q23 = FMA2(bb,EP[5][1],q23); q45 = FMA2(bb,EP[5][2],q45);
        q6 = fmaf(a5,E6[5],q6);
        bb = PK(p6,p6);
        q01 = FMA2(bb,EP[6][0],q01); q23 = FMA2(bb,EP[6][1],q23); q45 = FMA2(bb,EP[6][2],q45);
        q6 = fmaf(p6,E6[6],q6);
        q01 = MUL2(q01, PK(x0,x1));
        q23 = MUL2(q23, PK(x2,x3));
        q45 = MUL2(q45, PK(x4,x5));
        q6 *= x6;
        p01 = M ? q01 : p01;
        p23 = M ? q23 : p23;
        p45 = M ? q45 : p45;
        p6  = M ? q6  : p6;
    };

#define RENORM() do { \
    float a0,a1,a2,a3,a4,a5; \
    UPK(p01,a0,a1); UPK(p23,a2,a3); UPK(p45,a4,a5); \
    float mx = fmaxf(fmaxf(fmaxf(a0,a1), fmaxf(a2,a3)), fmaxf(fmaxf(a4,a5), p6)); \
    int ex = (__float_as_int(mx) >> 23) & 0xFF; \
    float inv = __int_as_float((254 - ex) << 23); \
    xsum += ex - 127; \
    u64 iv = PK(inv, inv); \
    p01 = MUL2(p01,iv); p23 = MUL2(p23,iv); p45 = MUL2(p45,iv); p6 *= inv; } while (0)

#define PROC8(ROWP, M0v, M1v) do { \
    STEP((ROWP)+0,  (M0v).x); STEP((ROWP)+7,  (M0v).y); \
    STEP((ROWP)+14, (M0v).z); STEP((ROWP)+21, (M0v).w); \
    STEP((ROWP)+28, (M1v).x); STEP((ROWP)+35, (M1v).y); \
    STEP((ROWP)+42, (M1v).z); STEP((ROWP)+49, (M1v).w); \
    RENORM(); } while (0)

    // ---- prologue ----
    STAGE(0); STAGE(1); STAGE(2);
    int4 mC0 = __ldg(mb4 + 0), mC1 = __ldg(mb4 + 1);
    CP_WAIT2(); __syncwarp();

    // ---- init (t=0) ----
    {
        float q[7];
#pragma unroll
        for (int j = 0; j < 7; j++) q[j] = __expf(__ldg(startT + j) + myrow0[j]);
        float mx = q[0];
#pragma unroll
        for (int j = 1; j < 7; j++) mx = fmaxf(mx, q[j]);
        int ex = (__float_as_int(mx) >> 23) & 0xFF;
        float inv = __int_as_float((254 - ex) << 23);
        xsum = ex - 127;
        p01 = PK(q[0]*inv, q[1]*inv);
        p23 = PK(q[2]*inv, q[3]*inv);
        p45 = PK(q[4]*inv, q[5]*inv);
        p6  = q[6]*inv;
    }

    // ---- macro 0: steps 1..7 ----
    STEP(myrow0+7,  mC0.y); STEP(myrow0+14, mC0.z); STEP(myrow0+21, mC0.w);
    STEP(myrow0+28, mC1.x); STEP(myrow0+35, mC1.y);
    STEP(myrow0+42, mC1.z); STEP(myrow0+49, mC1.w);
    RENORM();
    __syncwarp();
    STAGE(3);
    mC0 = __ldg(mb4 + 2); mC1 = __ldg(mb4 + 3);

    // ---- mainloop: macros 1..63 ----
#pragma unroll 1
    for (int m = 1; m < 64; m++) {
        int nidx = (m < 63) ? (2*m + 2) : (2*m);
        int4 mN0 = __ldg(mb4 + nidx), mN1 = __ldg(mb4 + nidx + 1);

        CP_WAIT2(); __syncwarp();
        const float* rowp = (m % 3 == 0) ? myrow0 : (m % 3 == 1) ? myrow1 : myrow2;
        PROC8(rowp, mC0, mC1);
        __syncwarp();
        if (m + 3 < 64) STAGE(m + 3);

        mC0 = mN0; mC1 = mN1;
    }

    // ---- finish: den only ----
    float a0,a1,a2,a3,a4,a5;
    UPK(p01,a0,a1); UPK(p23,a2,a3); UPK(p45,a4,a5);
    float acc =        a0 * __expf(__ldg(endT + 0));
    acc = fmaf(a1, __expf(__ldg(endT + 1)), acc);
    acc = fmaf(a2, __expf(__ldg(endT + 2)), acc);
    acc = fmaf(a3, __expf(__ldg(endT + 3)), acc);
    acc = fmaf(a4, __expf(__ldg(endT + 4)), acc);
    acc = fmaf(a5, __expf(__ldg(endT + 5)), acc);
    acc = fmaf(p6, __expf(__ldg(endT + 6)), acc);
    float den = __logf(acc) + (float)xsum * 0.69314718055994531f;

#pragma unroll
    for (int off = 16; off > 0; off >>= 1)
        den += __shfl_xor_sync(0xFFFFFFFFu, den, off);
    if (lane == 0) atomicAdd(out, den);

#undef STAGE
#undef RENORM
#undef PROC8
}

extern "C" void kernel_launch(void* const* d_in, const int* in_sizes, int n_in,
                              void* d_out, int out_size)
{
    const float* em     = (const float*)d_in[0];
    const int*   labels = (const int*)  d_in[1];
    const int*   mask   = (const int*)  d_in[2];
    const float* startT = (const float*)d_in[3];
    const float* endT   = (const float*)d_in[4];
    const float* trans  = (const float*)d_in[5];

    cudaMemsetAsync(d_out, 0, sizeof(float));
    crf_fwd_kernel<<<128, 96>>>(em, labels, mask, startT, endT, trans, (float*)d_out);
}

// round 6
// speedup vs baseline: 1.7194x; 1.7194x over previous
#include <cuda_runtime.h>

#define Tv 512
#define ROWW 60    // floats per emission smem row (56 data + 4 pad)
#define LROWW 20   // ints per label/mask smem row (8 lab + 8 msk + 4 pad)

typedef unsigned long long u64;

static __device__ __forceinline__ u64 PK(float a, float b) {
    u64 r; asm("mov.b64 %0,{%1,%2};" : "=l"(r) : "r"(__float_as_uint(a)), "r"(__float_as_uint(b))); return r;
}
static __device__ __forceinline__ void UPK(u64 v, float& a, float& b) {
    unsigned x, y; asm("mov.b64 {%0,%1},%2;" : "=r"(x), "=r"(y) : "l"(v));
    a = __uint_as_float(x); b = __uint_as_float(y);
}
static __device__ __forceinline__ u64 FMA2(u64 a, u64 b, u64 c) {
    u64 d; asm("fma.rn.f32x2 %0,%1,%2,%3;" : "=l"(d) : "l"(a), "l"(b), "l"(c)); return d;
}
static __device__ __forceinline__ u64 MUL2(u64 a, u64 b) {
    u64 d; asm("mul.rn.f32x2 %0,%1,%2;" : "=l"(d) : "l"(a), "l"(b)); return d;
}
static __device__ __forceinline__ void cpa16(void* dst, const void* src) {
    unsigned d = (unsigned)__cvta_generic_to_shared(dst);
    asm volatile("cp.async.cg.shared.global [%0], [%1], 16;" :: "r"(d), "l"(src));
}
#define CP_COMMIT() asm volatile("cp.async.commit_group;")
#define CP_WAIT2()  asm volatile("cp.async.wait_group 2;")

__global__ void __launch_bounds__(32, 1)
crf_fwd_kernel(const float* __restrict__ em,
               const int* __restrict__ labels,
               const int* __restrict__ mask,
               const float* __restrict__ startT,
               const float* __restrict__ endT,
               const float* __restrict__ trans,
               float* __restrict__ out)
{
    __shared__ float sm[3][64 * ROWW];     // 46 KB emission stages
    __shared__ int   lmem[3][64 * LROWW];  // 15 KB label/mask stages
    __shared__ float sTrans[49];

    const int lane = threadIdx.x;
    for (int i = lane; i < 49; i += 32) sTrans[i] = trans[i];
    __syncwarp();

    const int base = blockIdx.x * 64;             // this warp owns 64 sequences
    const float* emb  = em + (size_t)base * (Tv * 7);
    const int*   labb = labels + (size_t)base * Tv;
    const int*   mskb = mask   + (size_t)base * Tv;

    // exp(transitions) as duplicated-half pairs: EE[i][j] = (e, e)
    u64 EE[7][7];
#pragma unroll
    for (int i = 0; i < 7; i++)
#pragma unroll
        for (int j = 0; j < 7; j++) {
            float e = __expf(__ldg(&trans[i * 7 + j]));
            EE[i][j] = PK(e, e);
        }

#define STAGE(MM) do { \
    float* _eb = &sm[(MM) % 3][0]; int* _lb = &lmem[(MM) % 3][0]; \
    _Pragma("unroll") \
    for (int i = 0; i < 28; i++) { \
        int idx = i * 32 + lane; int r = (idx * 4682) >> 16; int c = idx - r * 14; \
        cpa16(_eb + r * ROWW + c * 4, emb + (size_t)r * (Tv * 7) + (MM) * 56 + c * 4); \
    } \
    _Pragma("unroll") \
    for (int i = 0; i < 8; i++) { \
        int idx = i * 32 + lane; int s = idx >> 2; int c = idx & 3; \
        const int* _src = (c < 2) ? (labb + (size_t)s * Tv + (MM) * 8 + (c & 1) * 4) \
                                  : (mskb + (size_t)s * Tv + (MM) * 8 + (c & 1) * 4); \
        cpa16(_lb + s * LROWW + c * 4, _src); \
    } \
    CP_COMMIT(); } while (0)

    u64 p[7];                 // forward state: (seqA, seqB) pairs
    int xsA = 0, xsB = 0;     // accumulated base-2 exponents
    float numA, numB;         // gold-path scores
    int prevA, prevB;

    // one recursion step for both sequences
    auto STEP = [&](const float* epA, const float* epB, int LA, int MA, int LB, int MB) {
        int LcA = LA < 0 ? 0 : LA, LcB = LB < 0 ? 0 : LB;
        float vA = sTrans[prevA * 7 + LcA] + epA[LcA];
        float vB = sTrans[prevB * 7 + LcB] + epB[LcB];
        numA += MA ? vA : 0.f;  prevA = MA ? LcA : prevA;
        numB += MB ? vB : 0.f;  prevB = MB ? LcB : prevB;

        u64 q[7];
#pragma unroll
        for (int j = 0; j < 7; j++) q[j] = MUL2(p[0], EE[0][j]);
#pragma unroll
        for (int i = 1; i < 7; i++)
#pragma unroll
            for (int j = 0; j < 7; j++) q[j] = FMA2(p[i], EE[i][j], q[j]);
#pragma unroll
        for (int j = 0; j < 7; j++)
            q[j] = MUL2(q[j], PK(__expf(epA[j]), __expf(epB[j])));

        unsigned mA32 = MA ? 0xFFFFFFFFu : 0u;
        unsigned mB32 = MB ? 0xFFFFFFFFu : 0u;
        u64 mm = ((u64)mB32 << 32) | mA32;
#pragma unroll
        for (int j = 0; j < 7; j++) p[j] = (q[j] & mm) | (p[j] & ~mm);
    };

#define RENORM() do { \
    float aA[7], aB[7]; \
    _Pragma("unroll") for (int j = 0; j < 7; j++) UPK(p[j], aA[j], aB[j]); \
    float mxA = aA[0], mxB = aB[0]; \
    _Pragma("unroll") for (int j = 1; j < 7; j++) { mxA = fmaxf(mxA, aA[j]); mxB = fmaxf(mxB, aB[j]); } \
    int exA = (__float_as_int(mxA) >> 23) & 0xFF; \
    int exB = (__float_as_int(mxB) >> 23) & 0xFF; \
    float invA = __int_as_float((254 - exA) << 23); \
    float invB = __int_as_float((254 - exB) << 23); \
    xsA += exA - 127; xsB += exB - 127; \
    u64 iv = PK(invA, invB); \
    _Pragma("unroll") for (int j = 0; j < 7; j++) p[j] = MUL2(p[j], iv); } while (0)

#define PROC8(ST) do { \
    const float* rA = &sm[ST][lane * ROWW]; \
    const float* rB = &sm[ST][(lane + 32) * ROWW]; \
    const int* lrA = &lmem[ST][lane * LROWW]; \
    const int* lrB = &lmem[ST][(lane + 32) * LROWW]; \
    { int4 la = *(const int4*)(lrA),     lb = *(const int4*)(lrB); \
      int4 ma = *(const int4*)(lrA + 8), mb = *(const int4*)(lrB + 8); \
      STEP(rA + 0,  rB + 0,  la.x, ma.x, lb.x, mb.x); \
      STEP(rA + 7,  rB + 7,  la.y, ma.y, lb.y, mb.y); \
      STEP(rA + 14, rB + 14, la.z, ma.z, lb.z, mb.z); \
      STEP(rA + 21, rB + 21, la.w, ma.w, lb.w, mb.w); } \
    { int4 la = *(const int4*)(lrA + 4),  lb = *(const int4*)(lrB + 4); \
      int4 ma = *(const int4*)(lrA + 12), mb = *(const int4*)(lrB + 12); \
      STEP(rA + 28, rB + 28, la.x, ma.x, lb.x, mb.x); \
      STEP(rA + 35, rB + 35, la.y, ma.y, lb.y, mb.y); \
      STEP(rA + 42, rB + 42, la.z, ma.z, lb.z, mb.z); \
      STEP(rA + 49, rB + 49, la.w, ma.w, lb.w, mb.w); } \
    RENORM(); } while (0)

    // ---- prologue: stage macros 0..2 ----
    STAGE(0); STAGE(1); STAGE(2);
    CP_WAIT2(); __syncwarp();

    // ---- init (t=0) + macro 0 steps 1..7 ----
    {
        const float* rA = &sm[0][lane * ROWW];
        const float* rB = &sm[0][(lane + 32) * ROWW];
        const int* lrA = &lmem[0][lane * LROWW];
        const int* lrB = &lmem[0][(lane + 32) * LROWW];

        float qA[7], qB[7];
#pragma unroll
        for (int j = 0; j < 7; j++) {
            float s = __ldg(startT + j);
            qA[j] = __expf(s + rA[j]);
            qB[j] = __expf(s + rB[j]);
        }
        float mxA = qA[0], mxB = qB[0];
#pragma unroll
        for (int j = 1; j < 7; j++) { mxA = fmaxf(mxA, qA[j]); mxB = fmaxf(mxB, qB[j]); }
        int exA = (__float_as_int(mxA) >> 23) & 0xFF;
        int exB = (__float_as_int(mxB) >> 23) & 0xFF;
        float invA = __int_as_float((254 - exA) << 23);
        float invB = __int_as_float((254 - exB) << 23);
        xsA = exA - 127; xsB = exB - 127;
#pragma unroll
        for (int j = 0; j < 7; j++) p[j] = PK(qA[j] * invA, qB[j] * invB);

        int4 la0 = *(const int4*)(lrA),     lb0 = *(const int4*)(lrB);
        int4 ma0 = *(const int4*)(lrA + 8), mb0 = *(const int4*)(lrB + 8);
        int L0A = la0.x < 0 ? 0 : la0.x;
        int L0B = lb0.x < 0 ? 0 : lb0.x;
        numA = __ldg(startT + L0A) + rA[L0A];  prevA = L0A;
        numB = __ldg(startT + L0B) + rB[L0B];  prevB = L0B;

        STEP(rA + 7,  rB + 7,  la0.y, ma0.y, lb0.y, mb0.y);
        STEP(rA + 14, rB + 14, la0.z, ma0.z, lb0.z, mb0.z);
        STEP(rA + 21, rB + 21, la0.w, ma0.w, lb0.w, mb0.w);

        int4 la1 = *(const int4*)(lrA + 4),  lb1 = *(const int4*)(lrB + 4);
        int4 ma1 = *(const int4*)(lrA + 12), mb1 = *(const int4*)(lrB + 12);
        STEP(rA + 28, rB + 28, la1.x, ma1.x, lb1.x, mb1.x);
        STEP(rA + 35, rB + 35, la1.y, ma1.y, lb1.y, mb1.y);
        STEP(rA + 42, rB + 42, la1.z, ma1.z, lb1.z, mb1.z);
        STEP(rA + 49, rB + 49, la1.w, ma1.w, lb1.w, mb1.w);
        RENORM();
    }
    __syncwarp();
    STAGE(3);

    // ---- mainloop: macros 1..63 ----
#pragma unroll 1
    for (int m = 1; m < 64; m++) {
        CP_WAIT2(); __syncwarp();
        PROC8(m % 3);
        __syncwarp();
        if (m + 3 < 64) STAGE(m + 3);
    }

    // ---- finish ----
    float aA[7], aB[7];
#pragma unroll
    for (int j = 0; j < 7; j++) UPK(p[j], aA[j], aB[j]);
    float accA = 0.f, accB = 0.f;
#pragma unroll
    for (int j = 0; j < 7; j++) {
        float ee = __expf(__ldg(endT + j));
        accA = fmaf(aA[j], ee, accA);
        accB = fmaf(aB[j], ee, accB);
    }
    const float LN2 = 0.69314718055994531f;
    float denA = __logf(accA) + (float)xsA * LN2;
    float denB = __logf(accB) + (float)xsB * LN2;
    numA += __ldg(endT + prevA);
    numB += __ldg(endT + prevB);
    float r = (denA - numA) + (denB - numB);

#pragma unroll
    for (int off = 16; off > 0; off >>= 1)
        r += __shfl_xor_sync(0xFFFFFFFFu, r, off);
    if (lane == 0) atomicAdd(out, r);

#undef STAGE
#undef RENORM
#undef PROC8
}

extern "C" void kernel_launch(void* const* d_in, const int* in_sizes, int n_in,
                              void* d_out, int out_size)
{
    const float* em     = (const float*)d_in[0];
    const int*   labels = (const int*)  d_in[1];
    const int*   mask   = (const int*)  d_in[2];
    const float* startT = (const float*)d_in[3];
    const float* endT   = (const float*)d_in[4];
    const float* trans  = (const float*)d_in[5];

    cudaMemsetAsync(d_out, 0, sizeof(float));
    crf_fwd_kernel<<<128, 32>>>(em, labels, mask, startT, endT, trans, (float*)d_out);
}